// round 15
// baseline (speedup 1.0000x reference)
#include <cuda_runtime.h>
#include <math.h>

// Fixed shapes from setup_inputs
#define BSZ 32
#define TT  50
#define CC  80
#define AA  85          // 5 + C
#define HH  76
#define WW  76
#define HWX (HH*WW)     // 5776
#define SIGMA_F 8.0f

#define BLK     256
#define NWARP   (BLK/32)                     // 8
#define GCHUNK  256                          // cells per batch per grid block
#define GXB     ((HWX + GCHUNK - 1) / GCHUNK) // 23
#define NPAIR   (BSZ/2)                      // 16 batch pairs
#define GRIDBLKS (GXB * NPAIR)               // 368
#define OBJS    4                            // obj blocks per batch
#define OBJBLKS (OBJS * BSZ)                 // 128
#define NBLOCKS (GRIDBLKS + OBJBLKS)         // 496

// ---------------- device scratch ----------------
__device__ int    g_neff[BSZ];
__device__ double g_noobj[16];
__device__ double g_acc[7];      // [0..3]=x,y,w,h [4]=conf_obj [5]=noobj_corr [6]=cls
__device__ unsigned int g_done;

// ---------------- math helpers ----------------
// robust softplus = log(1+exp(v)) = -clog(1-sigmoid(v)) = -clog(sigmoid(-v))
__device__ __forceinline__ float softplus_(float v) {
    return fmaxf(v, 0.0f) + __logf(1.0f + __expf(-fabsf(v)));
}
__device__ __forceinline__ float sigmoidf_(float v) {
    return __fdividef(1.0f, 1.0f + __expf(-v));
}
// bce(sigmoid(v), t) = t*softplus(-v) + (1-t)*softplus(v)
__device__ __forceinline__ float bce_logit_(float v, float t) {
    return t * softplus_(-v) + (1.0f - t) * softplus_(v);
}
__device__ __forceinline__ float sl1f_(float a, float b) {
    float d = fabsf(a - b);
    return (d < 1.0f) ? 0.5f * d * d : d - 0.5f;
}

// ---- deterministic target prep for one batch on one 64-thread group ----
// barbase / barbase+1 are the named-barrier ids for this group.
// s_box gets {3*gx1, gy1, 3*gx2, gy2} (x pre-scaled by 3 folds the IoU>=0.5 factor).
__device__ __forceinline__ void prep_targets(
    const float* __restrict__ tg0, int barbase, int ltid,
    float4* sbox, float* sa, int* skey, unsigned* smask,
    bool objfields, int* scell, float* stx, float* sty,
    float* stw, float* sth, float* ssc, int* scls)
{
    const int w2 = ltid >> 5, lane = ltid & 31;
    float gx = 0.f, gy = 0.f, gw = 0.f, gh = 0.f, t0 = 0.f, t3 = 0.f, t4 = 0.f;
    int gi = 0, gj = 0, mycell = 0;
    bool valid = false;
    if (ltid < TT) {
        const float* tg = tg0 + ltid * 5;
        t0 = tg[0];
        float t1 = tg[1], t2 = tg[2];
        t3 = tg[3]; t4 = tg[4];
        valid = ((t0 + t1 + t2 + t3 + t4) != 0.0f);
        gx = t1 * (float)WW;
        gy = t2 * (float)HH;
        gw = t3 * (float)WW;
        gh = t4 * (float)HH;
        gi = min(max((int)gx, 0), WW - 1);
        gj = min(max((int)gy, 0), HH - 1);
        mycell = gj * WW + gi;
    }
    if (w2 == 0) skey[lane] = valid ? mycell : -1;
    asm volatile("bar.sync %0, 64;" :: "r"(barbase) : "memory");

    bool eff = false;
    if (w2 == 0) {
        int key = valid ? mycell : (0x10000 + lane);
        unsigned mm = __match_any_sync(0xffffffffu, key);
        eff = valid && ((mm & ((1u << lane) - 1u)) == 0u);
    } else {
        int key = valid ? mycell : (0x20000 + lane);
        unsigned mm = __match_any_sync(0xffffffffu, key);
        bool dup = ((mm & ((1u << lane) - 1u)) != 0u);
        if (valid && !dup) {
            #pragma unroll 8
            for (int k = 0; k < 32; k++) dup |= (skey[k] == mycell);
        }
        eff = valid && !dup;
    }
    unsigned m = __ballot_sync(0xffffffffu, eff);
    if (lane == 0) smask[w2] = m;
    asm volatile("bar.sync %0, 64;" :: "r"(barbase + 1) : "memory");

    if (eff) {
        unsigned m0 = smask[0];
        int p = (w2 == 0) ? __popc(m0 & ((1u << lane) - 1u))
                          : __popc(m0) + __popc(smask[1] & ((1u << lane) - 1u));
        float gx3 = 3.0f * gx, gw3 = 3.0f * gw;
        sbox[p] = make_float4(fmaf(gw3, -0.5f, gx3), fmaf(gh, -0.5f, gy),
                              fmaf(gw3,  0.5f, gx3), fmaf(gh,  0.5f, gy));
        sa[p]   = gw * gh;
        if (objfields) {
            scell[p] = mycell;
            stx[p]   = gx - (float)gi;
            sty[p]   = gy - (float)gj;
            stw[p]   = __logf(gw / SIGMA_F + 1e-16f);
            sth[p]   = __logf(gh / SIGMA_F + 1e-16f);
            ssc[p]   = 2.0f - t3 * t4;
            scls[p]  = min(max((int)t0, 0), CC - 1);
        }
    }
}

// per-cell box setup: identical expression sequence in both roles (x pre-scaled by 3)
__device__ __forceinline__ void cell_box(
    float v0, float v1, float v2, float v3, int cell,
    float& px1, float& px2, float& py1, float& py2, float& pae)
{
    float xs = sigmoidf_(v0);
    float ys = sigmoidf_(v1);
    int i = cell % WW;
    int j = cell / WW;
    float px3 = 3.0f * (xs + (float)i);
    float py  = ys + (float)j;
    float pw  = __expf(v2) * SIGMA_F;
    float ph  = __expf(v3) * SIGMA_F;
    px1 = fmaf(pw, -1.5f, px3); px2 = fmaf(pw, 1.5f, px3);
    py1 = fmaf(ph, -0.5f, py);  py2 = fmaf(ph, 0.5f, py);
    pae = pw * ph + 1e-16f;
}

// max over targets of (3*iw*ih - ga); ignore <=> result >= pae
__device__ __forceinline__ float iou_max(
    const float4* sbox, const float* sa, int ne,
    float px1, float px2, float py1, float py2)
{
    float m1 = -1e30f, m2 = -1e30f;
    int e = 0;
    #pragma unroll 2
    for (; e + 1 < ne; e += 2) {
        float4 ba = sbox[e];
        float4 bb = sbox[e + 1];
        float ea0 = sa[e], ea1 = sa[e + 1];
        float iw0 = fminf(ba.z, px2) - fmaxf(ba.x, px1);
        float ih0 = fminf(ba.w, py2) - fmaxf(ba.y, py1);
        float iw1 = fminf(bb.z, px2) - fmaxf(bb.x, px1);
        float ih1 = fminf(bb.w, py2) - fmaxf(bb.y, py1);
        iw0 = fmaxf(iw0, 0.0f); ih0 = fmaxf(ih0, 0.0f);
        iw1 = fmaxf(iw1, 0.0f); ih1 = fmaxf(ih1, 0.0f);
        m1 = fmaxf(m1, fmaf(iw0, ih0, -ea0));
        m2 = fmaxf(m2, fmaf(iw1, ih1, -ea1));
    }
    if (e < ne) {
        float4 ba = sbox[e];
        float iw = fminf(ba.z, px2) - fmaxf(ba.x, px1);
        float ih = fminf(ba.w, py2) - fmaxf(ba.y, py1);
        iw = fmaxf(iw, 0.0f); ih = fmaxf(ih, 0.0f);
        m1 = fmaxf(m1, fmaf(iw, ih, -sa[e]));
    }
    return fmaxf(m1, m2);
}

// ---------------- single kernel, role-split blocks (1D grid) ----------------
__global__ __launch_bounds__(BLK) void yolo_one(const float* __restrict__ inp,
                                                const float* __restrict__ targets,
                                                float* __restrict__ out) {
    // batch-A target data (grid role: batch pr; obj role: batch b)
    __shared__ float4 s_boxA[TT];
    __shared__ float  s_aA[TT];
    // batch-B target data (grid role only)
    __shared__ float4 s_boxB[TT];
    __shared__ float  s_aB[TT];
    // obj-only fields (aliased onto A-batch)
    __shared__ int    s_cell[TT];
    __shared__ float  s_tx[TT], s_ty[TT], s_tw[TT], s_th[TT], s_sc[TT];
    __shared__ int    s_cls[TT];
    // prep temporaries
    __shared__ int      s_keyA[32], s_keyB[32];
    __shared__ unsigned s_maskA[2], s_maskB[2];
    __shared__ float    s_acc[7];
    __shared__ float    s_nacc;

    const int B    = blockIdx.x;
    const int tid  = threadIdx.x;
    const int wid  = tid >> 5;
    const int lane = tid & 31;
    const bool gridrole = (B < GRIDBLKS);

    if (tid == 0) s_nacc = 0.0f;
    if (tid < 7)  s_acc[tid] = 0.0f;

    if (gridrole) {
        // ============ grid role: one cell from batch A + one from batch B ============
        const int bx = B % GXB;
        const int pr = B / GXB;            // 0..15
        const int bA = pr, bB = pr + NPAIR;
        const float* baseA = inp + (size_t)bA * AA * HWX;
        const float* baseB = inp + (size_t)bB * AA * HWX;

        const int c  = bx * GCHUNK + tid;
        const bool cval = (c < HWX);
        const int cc = cval ? c : 0;

        // channel loads for both batches first (overlap everything below)
        float a0 = baseA[cc];
        float a1 = baseA[(size_t)1 * HWX + cc];
        float a2 = baseA[(size_t)2 * HWX + cc];
        float a3 = baseA[(size_t)3 * HWX + cc];
        float a4 = baseA[(size_t)4 * HWX + cc];
        float b0 = baseB[cc];
        float b1 = baseB[(size_t)1 * HWX + cc];
        float b2 = baseB[(size_t)2 * HWX + cc];
        float b3 = baseB[(size_t)3 * HWX + cc];
        float b4 = baseB[(size_t)4 * HWX + cc];

        // parallel preps: batch A on warps 0-1 (bars 1,2), batch B on warps 2-3 (bars 3,4)
        if (tid < 64) {
            prep_targets(targets + (size_t)bA * TT * 5, 1, tid,
                         s_boxA, s_aA, s_keyA, s_maskA,
                         false, 0, 0, 0, 0, 0, 0, 0);
        } else if (tid < 128) {
            prep_targets(targets + (size_t)bB * TT * 5, 3, tid - 64,
                         s_boxB, s_aB, s_keyB, s_maskB,
                         false, 0, 0, 0, 0, 0, 0, 0);
        }

        // box setup + hoisted softplus (warps 4-7 do this while 0-3 prep)
        float pxa1, pxa2, pya1, pya2, paeA;
        float pxb1, pxb2, pyb1, pyb2, paeB;
        cell_box(a0, a1, a2, a3, cc, pxa1, pxa2, pya1, pya2, paeA);
        cell_box(b0, b1, b2, b3, cc, pxb1, pxb2, pyb1, pyb2, paeB);
        float spA = softplus_(a4);
        float spB = softplus_(b4);
        __syncthreads();

        const int neA = __popc(s_maskA[0]) + __popc(s_maskA[1]);
        const int neB = __popc(s_maskB[0]) + __popc(s_maskB[1]);

        float mA = iou_max(s_boxA, s_aA, neA, pxa1, pxa2, pya1, pya2);
        float mB = iou_max(s_boxB, s_aB, neB, pxb1, pxb2, pyb1, pyb2);

        float acc = 0.0f;
        if (cval && (mA < paeA)) acc += spA;
        if (cval && (mB < paeB)) acc += spB;

        #pragma unroll
        for (int o = 16; o > 0; o >>= 1) acc += __shfl_down_sync(0xffffffffu, acc, o);
        if (lane == 0 && acc != 0.0f) atomicAdd(&s_nacc, acc);
        __syncthreads();
        if (tid == 0 && s_nacc != 0.0f)
            atomicAdd(&g_noobj[B & 15], (double)s_nacc);
    } else {
        // ============ obj role: OBJS blocks per batch, warp per target ============
        const int t     = B - GRIDBLKS;
        const int b     = t / OBJS;
        const int slice = t % OBJS;
        const float* bbase = inp + (size_t)b * AA * HWX;

        if (tid < 64) {
            prep_targets(targets + (size_t)b * TT * 5, 1, tid,
                         s_boxA, s_aA, s_keyA, s_maskA,
                         true, s_cell, s_tx, s_ty, s_tw, s_th, s_sc, s_cls);
        }
        __syncthreads();
        const int ne = __popc(s_maskA[0]) + __popc(s_maskA[1]);
        if (slice == 0 && tid == 0) g_neff[b] = ne;

        for (int e = slice * NWARP + wid; e < ne; e += OBJS * NWARP) {
            const int cell = s_cell[e];
            const float* base = bbase + cell;

            float v0 = base[0];
            float v1 = base[(size_t)1 * HWX];
            float v2 = base[(size_t)2 * HWX];
            float v3 = base[(size_t)3 * HWX];
            float v4 = base[(size_t)4 * HWX];

            // identical pred-box expressions as grid role -> identical ignore test
            float opx1, opx2, opy1, opy2, opae;
            cell_box(v0, v1, v2, v3, cell, opx1, opx2, opy1, opy2, opae);

            bool ig = false;
            for (int k = lane; k < ne; k += 32) {
                float4 bk = s_boxA[k];
                float iw = fminf(bk.z, opx2) - fmaxf(bk.x, opx1);
                float ih = fminf(bk.w, opy2) - fmaxf(bk.y, opy1);
                iw = fmaxf(iw, 0.0f);
                ih = fmaxf(ih, 0.0f);
                ig |= (fmaf(iw, ih, -s_aA[k]) >= opae);
            }
            ig = (__ballot_sync(0xffffffffu, ig) != 0u);

            // class BCE lane-parallel over 80 classes (scattered loads, MLP across lanes)
            const int cls = s_cls[e];
            float scl = 0.0f;
            for (int cch = lane; cch < CC; cch += 32) {
                float vc = base[(size_t)(5 + cch) * HWX];
                scl += (cch == cls) ? softplus_(-vc) : softplus_(vc);
            }
            #pragma unroll
            for (int o = 16; o > 0; o >>= 1) scl += __shfl_down_sync(0xffffffffu, scl, o);

            if (lane == 0) {
                float sc = s_sc[e];
                atomicAdd(&s_acc[0], sc * bce_logit_(v0, s_tx[e]));
                atomicAdd(&s_acc[1], sc * bce_logit_(v1, s_ty[e]));
                atomicAdd(&s_acc[2], sc * sl1f_(v2, s_tw[e]));
                atomicAdd(&s_acc[3], sc * sl1f_(v3, s_th[e]));
                atomicAdd(&s_acc[4], softplus_(-v4));          // -clog(conf) at obj cell
                if (!ig) atomicAdd(&s_acc[5], softplus_(v4));  // noobj over-count correction
                atomicAdd(&s_acc[6], scl);
            }
        }
        __syncthreads();
        if (tid < 7 && s_acc[tid] != 0.0f) atomicAdd(&g_acc[tid], (double)s_acc[tid]);
    }

    // ---- finalize in the last-arriving block ----
    __shared__ bool s_last;
    if (tid == 0) {
        __threadfence();
        unsigned int ticket = atomicAdd(&g_done, 1u);
        s_last = (ticket == (unsigned int)(NBLOCKS - 1));
    }
    __syncthreads();
    if (s_last && tid == 0) {
        __threadfence();
        volatile double* acc = g_acc;
        int nobj = 0;
        for (int k = 0; k < BSZ; k++) nobj += g_neff[k];
        double noobj_sum = 0.0;
        for (int k = 0; k < 16; k++) noobj_sum += g_noobj[k];
        double inv = 1.0 / (double)nobj;
        double lx = acc[0] * inv;
        double ly = acc[1] * inv;
        double lw = acc[2] * inv;
        double lh = acc[3] * inv;
        double lconf = (acc[4] + 0.5 * (noobj_sum - acc[5])) * inv;
        double lcls  = (nobj > 0) ? acc[6] * inv : 0.0;  // sum(tcls) == n_obj
        double loss = lx + ly + lw + lh + lconf + lcls;
        out[0] = (float)loss;
        out[1] = (float)lx;
        out[2] = (float)ly;
        out[3] = (float)lw;
        out[4] = (float)lh;
        out[5] = (float)lconf;
        out[6] = (float)lcls;
        // reset for next graph replay
        for (int k = 0; k < 7;  k++) g_acc[k]   = 0.0;
        for (int k = 0; k < 16; k++) g_noobj[k] = 0.0;
        g_done = 0u;
    }
}

// ---------------- launch ----------------
extern "C" void kernel_launch(void* const* d_in, const int* in_sizes, int n_in,
                              void* d_out, int out_size) {
    const float* inp     = (const float*)d_in[0];   // [32, 85, 76, 76]
    const float* targets = (const float*)d_in[1];   // [32, 50, 5]
    float* out = (float*)d_out;

    yolo_one<<<NBLOCKS, BLK>>>(inp, targets, out);
}

// round 16
// speedup vs baseline: 1.1487x; 1.1487x over previous
#include <cuda_runtime.h>
#include <math.h>

// Fixed shapes from setup_inputs
#define BSZ 32
#define TT  50
#define CC  80
#define AA  85          // 5 + C
#define HH  76
#define WW  76
#define HWX (HH*WW)     // 5776
#define SIGMA_F 8.0f

#define BLK    256
#define NWARP  (BLK/32)                    // 8
#define BILP   2
#define CHUNK  (BLK*BILP)                  // 512
#define GXB    ((HWX + CHUNK - 1) / CHUNK) // 12 grid-role x-slices
#define OBJS   4                           // obj-role blocks per batch
#define GXT    (GXB + OBJS)                // 16
#define NBLOCKS (GXT * BSZ)                // 512

// ---------------- device scratch ----------------
__device__ int    g_neff[BSZ];
__device__ double g_noobj[16];
__device__ double g_acc[7];      // [0..3]=x,y,w,h [4]=conf_obj [5]=noobj_corr [6]=cls
__device__ unsigned int g_done;

// ---------------- math helpers ----------------
// robust softplus = log(1+exp(v)) = -clog(1-sigmoid(v)) = -clog(sigmoid(-v))
__device__ __forceinline__ float softplus_(float v) {
    return fmaxf(v, 0.0f) + __logf(1.0f + __expf(-fabsf(v)));
}
__device__ __forceinline__ float sigmoidf_(float v) {
    return __fdividef(1.0f, 1.0f + __expf(-v));
}
// bce(sigmoid(v), t) = t*softplus(-v) + (1-t)*softplus(v)
__device__ __forceinline__ float bce_logit_(float v, float t) {
    return t * softplus_(-v) + (1.0f - t) * softplus_(v);
}
__device__ __forceinline__ float sl1f_(float a, float b) {
    float d = fabsf(a - b);
    return (d < 1.0f) ? 0.5f * d * d : d - 0.5f;
}

// ---------------- single kernel, role-split blocks ----------------
__global__ __launch_bounds__(BLK) void yolo_one(const float* __restrict__ inp,
                                                const float* __restrict__ targets,
                                                float* __restrict__ out) {
    // compacted effective targets (DETERMINISTIC order by original index)
    // s_box = {3*gx1, gy1, 3*gx2, gy2}  (x pre-scaled by 3 folds the IoU>=0.5 factor)
    __shared__ float4 s_box[TT];
    __shared__ float  s_a[TT];
    __shared__ int    s_cell[TT];                                       // obj role only
    __shared__ float  s_tx[TT], s_ty[TT], s_tw[TT], s_th[TT], s_sc[TT]; // obj role only
    __shared__ int    s_cls[TT];                                        // obj role only
    // prep temporaries
    __shared__ int      s_key[32];
    __shared__ unsigned s_mask[2];
    __shared__ float    s_acc[7];

    const int bx  = blockIdx.x;   // 0..GXB-1 grid role, GXB..GXT-1 obj role
    const int b   = blockIdx.y;
    const int tid = threadIdx.x;
    const int wid  = tid >> 5;
    const int lane = tid & 31;
    const bool gridrole = (bx < GXB);

    if (!gridrole && tid < 7) s_acc[tid] = 0.0f;

    const float* bbase = inp + (size_t)b * AA * HWX;

    // ---- grid-role channel loads first (overlap with everything below) ----
    const int c0 = bx * CHUNK + 2 * tid;   // cells c0, c0+1 (HWX even)
    bool cval = false;
    float2 V0, V1, V2, V3, V4;
    if (gridrole) {
        cval = (c0 < HWX);
        const int cc = cval ? c0 : 0;
        V0 = *(const float2*)(bbase + cc);
        V1 = *(const float2*)(bbase + (size_t)1 * HWX + cc);
        V2 = *(const float2*)(bbase + (size_t)2 * HWX + cc);
        V3 = *(const float2*)(bbase + (size_t)3 * HWX + cc);
        V4 = *(const float2*)(bbase + (size_t)4 * HWX + cc);
    }

    // ---- prep on warps 0-1 only (named barriers; warps 2-7 fly past) ----
    float gx = 0.f, gy = 0.f, gw = 0.f, gh = 0.f, t0 = 0.f, t3 = 0.f, t4 = 0.f;
    int gi = 0, gj = 0, mycell = 0;
    if (tid < 64) {
        bool valid = false;
        if (tid < TT) {
            const float* tg = targets + ((size_t)b * TT + tid) * 5;
            t0 = tg[0];
            float t1 = tg[1], t2 = tg[2];
            t3 = tg[3]; t4 = tg[4];
            valid = ((t0 + t1 + t2 + t3 + t4) != 0.0f);
            gx = t1 * (float)WW;
            gy = t2 * (float)HH;
            gw = t3 * (float)WW;
            gh = t4 * (float)HH;
            gi = min(max((int)gx, 0), WW - 1);
            gj = min(max((int)gy, 0), HH - 1);
            mycell = gj * WW + gi;
        }
        if (wid == 0) s_key[lane] = valid ? mycell : -1;
        asm volatile("bar.sync 1, 64;" ::: "memory");

        // dup check (deterministic): first occurrence among VALID targets wins
        bool eff = false;
        if (wid == 0) {
            int key = valid ? mycell : (0x10000 + lane);
            unsigned mm = __match_any_sync(0xffffffffu, key);
            eff = valid && ((mm & ((1u << lane) - 1u)) == 0u);
        } else {
            int key = valid ? mycell : (0x20000 + lane);
            unsigned mm = __match_any_sync(0xffffffffu, key);
            bool dup = ((mm & ((1u << lane) - 1u)) != 0u);
            if (valid && !dup) {
                #pragma unroll 8
                for (int k = 0; k < 32; k++) dup |= (s_key[k] == mycell);
            }
            eff = valid && !dup;
        }
        unsigned m = __ballot_sync(0xffffffffu, eff);
        if (lane == 0) s_mask[wid] = m;
        asm volatile("bar.sync 2, 64;" ::: "memory");

        if (eff) {
            const unsigned m0 = s_mask[0];
            int p = (wid == 0) ? __popc(m0 & ((1u << lane) - 1u))
                               : __popc(m0) + __popc(s_mask[1] & ((1u << lane) - 1u));
            // x coords pre-scaled by 3
            float gx3 = 3.0f * gx;
            float gw3 = 3.0f * gw;
            s_box[p] = make_float4(fmaf(gw3, -0.5f, gx3), fmaf(gh, -0.5f, gy),
                                   fmaf(gw3,  0.5f, gx3), fmaf(gh,  0.5f, gy));
            s_a[p]   = gw * gh;
            if (!gridrole) {   // obj-only fields
                s_cell[p]= mycell;
                s_tx[p]  = gx - (float)gi;
                s_ty[p]  = gy - (float)gj;
                s_tw[p]  = __logf(gw / SIGMA_F + 1e-16f);
                s_th[p]  = __logf(gh / SIGMA_F + 1e-16f);
                s_sc[p]  = 2.0f - t3 * t4;
                s_cls[p] = min(max((int)t0, 0), CC - 1);
            }
        }
    }

    // ---- box setup + hoisted softplus (warps 2-7 do this while 0-1 prep) ----
    float pae[BILP], sp[BILP];
    float px1[BILP], px2[BILP], py1[BILP], py2[BILP];   // x pre-scaled by 3
    if (gridrole) {
        const int cc = cval ? c0 : 0;
        const float v0s[BILP] = {V0.x, V0.y};
        const float v1s[BILP] = {V1.x, V1.y};
        const float v2s[BILP] = {V2.x, V2.y};
        const float v3s[BILP] = {V3.x, V3.y};
        const float v4s[BILP] = {V4.x, V4.y};
        #pragma unroll
        for (int u = 0; u < BILP; u++) {
            int cell = cc + u;
            float xs = sigmoidf_(v0s[u]);
            float ys = sigmoidf_(v1s[u]);
            int i = cell % WW;
            int j = cell / WW;
            float px3 = 3.0f * (xs + (float)i);
            float py  = ys + (float)j;
            float pw  = __expf(v2s[u]) * SIGMA_F;
            float ph  = __expf(v3s[u]) * SIGMA_F;
            px1[u] = fmaf(pw, -1.5f, px3); px2[u] = fmaf(pw, 1.5f, px3);
            py1[u] = fmaf(ph, -0.5f, py);  py2[u] = fmaf(ph, 0.5f, py);
            pae[u] = pw * ph + 1e-16f;
            sp[u]  = softplus_(v4s[u]);    // hoisted; selected after the loop
        }
    }
    __syncthreads();   // single full barrier: SMEM target data ready
    const int ne = __popc(s_mask[0]) + __popc(s_mask[1]);

    if (gridrole) {
        // ================= grid role: uniform noobj + ignore =================
        float m_a[BILP], m_b[BILP];
        #pragma unroll
        for (int u = 0; u < BILP; u++) { m_a[u] = -1e30f; m_b[u] = -1e30f; }

        int e = 0;
        #pragma unroll 2
        for (; e + 1 < ne; e += 2) {
            float4 ba = s_box[e];
            float4 bb = s_box[e + 1];
            float  eaa = s_a[e];
            float  eab = s_a[e + 1];
            #pragma unroll
            for (int u = 0; u < BILP; u++) {
                float iw0 = fminf(ba.z, px2[u]) - fmaxf(ba.x, px1[u]);  // = 3*iw
                float ih0 = fminf(ba.w, py2[u]) - fmaxf(ba.y, py1[u]);
                float iw1 = fminf(bb.z, px2[u]) - fmaxf(bb.x, px1[u]);
                float ih1 = fminf(bb.w, py2[u]) - fmaxf(bb.y, py1[u]);
                iw0 = fmaxf(iw0, 0.0f); ih0 = fmaxf(ih0, 0.0f);
                iw1 = fmaxf(iw1, 0.0f); ih1 = fmaxf(ih1, 0.0f);
                // iou >= 0.5 <=> 3*inter - ga >= pa + 1e-16
                m_a[u] = fmaxf(m_a[u], fmaf(iw0, ih0, -eaa));
                m_b[u] = fmaxf(m_b[u], fmaf(iw1, ih1, -eab));
            }
        }
        if (e < ne) {
            float4 ba = s_box[e];
            float  ea = s_a[e];
            #pragma unroll
            for (int u = 0; u < BILP; u++) {
                float iw = fminf(ba.z, px2[u]) - fmaxf(ba.x, px1[u]);
                float ih = fminf(ba.w, py2[u]) - fmaxf(ba.y, py1[u]);
                iw = fmaxf(iw, 0.0f); ih = fmaxf(ih, 0.0f);
                m_a[u] = fmaxf(m_a[u], fmaf(iw, ih, -ea));
            }
        }

        float acc = 0.0f;
        #pragma unroll
        for (int u = 0; u < BILP; u++) {
            float m = fmaxf(m_a[u], m_b[u]);
            if (cval && (m < pae[u])) acc += sp[u];
        }

        #pragma unroll
        for (int o = 16; o > 0; o >>= 1) acc += __shfl_down_sync(0xffffffffu, acc, o);
        // per-warp global atomic: skips a shared stage + a full barrier on the tail
        if (lane == 0 && acc != 0.0f)
            atomicAdd(&g_noobj[((b * GXB + bx) * NWARP + wid) & 15], (double)acc);
    } else {
        // ================= obj role: OBJS blocks per batch, warp per target =================
        const int slice = bx - GXB;          // 0..OBJS-1
        if (slice == 0 && tid == 0) g_neff[b] = ne;

        for (int e = slice * NWARP + wid; e < ne; e += OBJS * NWARP) {
            const int cell = s_cell[e];
            const float* base = bbase + cell;

            float v0 = base[0];
            float v1 = base[(size_t)1 * HWX];
            float v2 = base[(size_t)2 * HWX];
            float v3 = base[(size_t)3 * HWX];
            float v4 = base[(size_t)4 * HWX];

            // identical pred-box expressions as grid role -> identical ignore test
            float xs = sigmoidf_(v0);
            float ys = sigmoidf_(v1);
            int i = cell % WW;
            int j = cell / WW;
            float px3 = 3.0f * (xs + (float)i);
            float py  = ys + (float)j;
            float pw  = __expf(v2) * SIGMA_F;
            float ph  = __expf(v3) * SIGMA_F;
            float opx1 = fmaf(pw, -1.5f, px3), opx2 = fmaf(pw, 1.5f, px3);
            float opy1 = fmaf(ph, -0.5f, py),  opy2 = fmaf(ph, 0.5f, py);
            float opae = pw * ph + 1e-16f;

            bool ig = false;
            for (int k = lane; k < ne; k += 32) {
                float4 bk = s_box[k];
                float iw = fminf(bk.z, opx2) - fmaxf(bk.x, opx1);
                float ih = fminf(bk.w, opy2) - fmaxf(bk.y, opy1);
                iw = fmaxf(iw, 0.0f);
                ih = fmaxf(ih, 0.0f);
                ig |= (fmaf(iw, ih, -s_a[k]) >= opae);
            }
            ig = (__ballot_sync(0xffffffffu, ig) != 0u);

            // class BCE lane-parallel over 80 classes (scattered loads, MLP across lanes)
            const int cls = s_cls[e];
            float scl = 0.0f;
            for (int c = lane; c < CC; c += 32) {
                float vc = base[(size_t)(5 + c) * HWX];
                scl += (c == cls) ? softplus_(-vc) : softplus_(vc);
            }
            #pragma unroll
            for (int o = 16; o > 0; o >>= 1) scl += __shfl_down_sync(0xffffffffu, scl, o);

            if (lane == 0) {
                float sc = s_sc[e];
                atomicAdd(&s_acc[0], sc * bce_logit_(v0, s_tx[e]));
                atomicAdd(&s_acc[1], sc * bce_logit_(v1, s_ty[e]));
                atomicAdd(&s_acc[2], sc * sl1f_(v2, s_tw[e]));
                atomicAdd(&s_acc[3], sc * sl1f_(v3, s_th[e]));
                atomicAdd(&s_acc[4], softplus_(-v4));          // -clog(conf) at obj cell
                if (!ig) atomicAdd(&s_acc[5], softplus_(v4));  // noobj over-count correction
                atomicAdd(&s_acc[6], scl);
            }
        }
        __syncthreads();
        if (tid < 7 && s_acc[tid] != 0.0f) atomicAdd(&g_acc[tid], (double)s_acc[tid]);
    }

    // ---- finalize in the last-arriving block ----
    __shared__ bool s_last;
    if (tid == 0) {
        __threadfence();
        unsigned int ticket = atomicAdd(&g_done, 1u);
        s_last = (ticket == (unsigned int)(NBLOCKS - 1));
    }
    __syncthreads();
    if (s_last && tid == 0) {
        __threadfence();
        volatile double* acc = g_acc;
        int nobj = 0;
        for (int k = 0; k < BSZ; k++) nobj += g_neff[k];
        double noobj_sum = 0.0;
        for (int k = 0; k < 16; k++) noobj_sum += g_noobj[k];
        double inv = 1.0 / (double)nobj;
        double lx = acc[0] * inv;
        double ly = acc[1] * inv;
        double lw = acc[2] * inv;
        double lh = acc[3] * inv;
        double lconf = (acc[4] + 0.5 * (noobj_sum - acc[5])) * inv;
        double lcls  = (nobj > 0) ? acc[6] * inv : 0.0;  // sum(tcls) == n_obj
        double loss = lx + ly + lw + lh + lconf + lcls;
        out[0] = (float)loss;
        out[1] = (float)lx;
        out[2] = (float)ly;
        out[3] = (float)lw;
        out[4] = (float)lh;
        out[5] = (float)lconf;
        out[6] = (float)lcls;
        // reset for next graph replay
        for (int k = 0; k < 7;  k++) g_acc[k]   = 0.0;
        for (int k = 0; k < 16; k++) g_noobj[k] = 0.0;
        g_done = 0u;
    }
}

// ---------------- launch ----------------
extern "C" void kernel_launch(void* const* d_in, const int* in_sizes, int n_in,
                              void* d_out, int out_size) {
    const float* inp     = (const float*)d_in[0];   // [32, 85, 76, 76]
    const float* targets = (const float*)d_in[1];   // [32, 50, 5]
    float* out = (float*)d_out;

    dim3 grid(GXT, BSZ);
    yolo_one<<<grid, BLK>>>(inp, targets, out);
}